// round 1
// baseline (speedup 1.0000x reference)
#include <cuda_runtime.h>
#include <cuda_bf16.h>

#define B_   8
#define S_   1024
#define IN_  768
#define H_   8
#define F_   64
#define HF_  512
#define ALPHA_ 0.2f

// Scratch (no allocations allowed): Wh = X@W, plus packed per-(b,h) attention vectors.
__device__ float  g_Wh[(size_t)B_ * S_ * HF_];          // [row][h*64+f], 16.8 MB
__device__ float4 g_ipack[B_ * H_ * S_];                // (src, exp(src), exp(a*src), 0)
__device__ float4 g_jpack[B_ * H_ * S_];                // (dst, m*exp(dst), m*exp(a*dst), 0)

// ---------------------------------------------------------------------------
// K1: Wh = X(8192x768) @ W(768x512), fp32, 128x128 tile, BK=16, 8x8/thread.
// ---------------------------------------------------------------------------
__global__ void __launch_bounds__(256) gemm_wh_kernel(const float* __restrict__ X,
                                                      const float* __restrict__ W)
{
    __shared__ float As[16][132];   // transposed A tile (+4 pad)
    __shared__ float Bs[16][128];

    const int t  = threadIdx.x;
    const int tx = t & 15;          // f-group: f = tx*8
    const int ty = t >> 4;          // i-group: i = ty*8
    const int i0 = blockIdx.y * 128;
    const int f0 = blockIdx.x * 128;

    float acc[8][8];
#pragma unroll
    for (int ii = 0; ii < 8; ii++)
#pragma unroll
        for (int ff = 0; ff < 8; ff++) acc[ii][ff] = 0.f;

    const int ar = t >> 2;            // 0..63
    const int aq = (t & 3) * 4;       // 0,4,8,12
    const int br = t >> 5;            // 0..7
    const int bq = (t & 31) * 4;      // 0..124

    for (int k0 = 0; k0 < IN_; k0 += 16) {
        __syncthreads();
        // A tile: 128 rows x 16 k
        float4 v0 = *(const float4*)(X + (size_t)(i0 + ar) * IN_ + k0 + aq);
        float4 v1 = *(const float4*)(X + (size_t)(i0 + ar + 64) * IN_ + k0 + aq);
        As[aq + 0][ar] = v0.x; As[aq + 1][ar] = v0.y;
        As[aq + 2][ar] = v0.z; As[aq + 3][ar] = v0.w;
        As[aq + 0][ar + 64] = v1.x; As[aq + 1][ar + 64] = v1.y;
        As[aq + 2][ar + 64] = v1.z; As[aq + 3][ar + 64] = v1.w;
        // B tile: 16 k x 128 f
        *(float4*)&Bs[br][bq]     = *(const float4*)(W + (size_t)(k0 + br) * HF_ + f0 + bq);
        *(float4*)&Bs[br + 8][bq] = *(const float4*)(W + (size_t)(k0 + br + 8) * HF_ + f0 + bq);
        __syncthreads();

#pragma unroll
        for (int k = 0; k < 16; k++) {
            float a[8], b[8];
            *(float4*)(a)     = *(float4*)&As[k][ty * 8];
            *(float4*)(a + 4) = *(float4*)&As[k][ty * 8 + 4];
            *(float4*)(b)     = *(float4*)&Bs[k][tx * 8];
            *(float4*)(b + 4) = *(float4*)&Bs[k][tx * 8 + 4];
#pragma unroll
            for (int ii = 0; ii < 8; ii++)
#pragma unroll
                for (int ff = 0; ff < 8; ff++)
                    acc[ii][ff] += a[ii] * b[ff];
        }
    }

#pragma unroll
    for (int ii = 0; ii < 8; ii++) {
        float* cp = g_Wh + (size_t)(i0 + ty * 8 + ii) * HF_ + f0 + tx * 8;
        *(float4*)(cp)     = make_float4(acc[ii][0], acc[ii][1], acc[ii][2], acc[ii][3]);
        *(float4*)(cp + 4) = make_float4(acc[ii][4], acc[ii][5], acc[ii][6], acc[ii][7]);
    }
}

// ---------------------------------------------------------------------------
// K2: per (row,h): src = Wh.a_src, dst = Wh.a_dst; pack exp factors.
// One warp per (row,h) task; 8 warps/block; grid = 8192.
// ---------------------------------------------------------------------------
__global__ void __launch_bounds__(256) srcdst_kernel(const int* __restrict__ mask,
                                                     const float* __restrict__ a)
{
    __shared__ float asrc[64], adst[64];
    const int t = threadIdx.x;
    if (t < 64)       asrc[t]      = a[t];
    else if (t < 128) adst[t - 64] = a[t];
    __syncthreads();

    const int lane = t & 31;
    const int task = blockIdx.x * 8 + (t >> 5);     // 0..65535
    const int row  = task >> 3;
    const int h    = task & 7;

    float2 v = *(const float2*)(g_Wh + (size_t)row * HF_ + h * F_ + lane * 2);
    float s = v.x * asrc[lane * 2] + v.y * asrc[lane * 2 + 1];
    float d = v.x * adst[lane * 2] + v.y * adst[lane * 2 + 1];
#pragma unroll
    for (int o = 16; o; o >>= 1) {
        s += __shfl_xor_sync(0xffffffffu, s, o);
        d += __shfl_xor_sync(0xffffffffu, d, o);
    }
    if (lane == 0) {
        const int b = row >> 10, i = row & 1023;
        const int idx = (b * H_ + h) * S_ + i;
        g_ipack[idx] = make_float4(s, expf(s), expf(ALPHA_ * s), 0.f);
        const float m = mask[row] ? 1.f : 0.f;
        g_jpack[idx] = make_float4(d, m * expf(d), m * expf(ALPHA_ * d), 0.f);
    }
}

// ---------------------------------------------------------------------------
// K3: attention + aggregation. Block = (i-tile of 128, h, b); 128 threads;
// each thread owns 16 i-rows x 4 f-cols. Inner weight needs NO exp:
//   w = (s_i + d_j >= 0) ? exp(s_i)*exp(d_j) : exp(a s_i)*exp(a d_j)
// Every thread sweeps all j, so Z is complete per-thread (no reduction).
// ---------------------------------------------------------------------------
__global__ void __launch_bounds__(128) attn_kernel(float* __restrict__ out)
{
    __shared__ float4 whs[128][16];   // [j][f-quad]
    __shared__ float4 jsh[128];

    const int b = blockIdx.z, h = blockIdx.y;
    const int t  = threadIdx.x;
    const int tx = t & 15;            // f = tx*4
    const int ty = t >> 4;            // i-subgroup: 16 rows each
    const int bh = b * H_ + h;
    const int i0 = blockIdx.x * 128 + ty * 16;

    float sreg[16], e1s[16], eas[16], z[16];
    float acc[16][4];
#pragma unroll
    for (int ii = 0; ii < 16; ii++) {
        float4 p = g_ipack[bh * S_ + i0 + ii];
        sreg[ii] = p.x; e1s[ii] = p.y; eas[ii] = p.z;
        z[ii] = 0.f;
        acc[ii][0] = 0.f; acc[ii][1] = 0.f; acc[ii][2] = 0.f; acc[ii][3] = 0.f;
    }

    const float* whbase = g_Wh + (size_t)b * S_ * HF_ + h * F_;

    for (int jt = 0; jt < 8; jt++) {
        const int j0 = jt * 128;
        __syncthreads();
#pragma unroll
        for (int p = 0; p < 16; p++) {
            int idx = p * 128 + t;
            int r = idx >> 4, q = idx & 15;
            whs[r][q] = *(const float4*)(whbase + (size_t)(j0 + r) * HF_ + q * 4);
        }
        jsh[t] = g_jpack[bh * S_ + j0 + t];
        __syncthreads();

#pragma unroll 2
        for (int jj = 0; jj < 128; jj++) {
            const float4 jp = jsh[jj];
            const float4 wv = whs[jj][tx];
#pragma unroll
            for (int ii = 0; ii < 16; ii++) {
                const bool pos = (sreg[ii] + jp.x) >= 0.f;
                const float w = (pos ? e1s[ii] : eas[ii]) * (pos ? jp.y : jp.z);
                z[ii] += w;
                acc[ii][0] += w * wv.x;
                acc[ii][1] += w * wv.y;
                acc[ii][2] += w * wv.z;
                acc[ii][3] += w * wv.w;
            }
        }
    }

    float* ob = out + (size_t)b * S_ * HF_ + h * F_ + tx * 4;
#pragma unroll
    for (int ii = 0; ii < 16; ii++) {
        const float inv = 1.f / z[ii];
        *(float4*)(ob + (size_t)(i0 + ii) * HF_) =
            make_float4(acc[ii][0] * inv, acc[ii][1] * inv,
                        acc[ii][2] * inv, acc[ii][3] * inv);
    }
}

// ---------------------------------------------------------------------------
extern "C" void kernel_launch(void* const* d_in, const int* in_sizes, int n_in,
                              void* d_out, int out_size)
{
    const float* X    = (const float*)d_in[0];   // node_features (8,1024,768)
    const int*   mask = (const int*)  d_in[1];   // attention_mask (8,1024)
    const float* W    = (const float*)d_in[2];   // (768,512)
    const float* a    = (const float*)d_in[3];   // (128,)
    float*       out  = (float*)d_out;           // (8,1024,512)

    gemm_wh_kernel<<<dim3(HF_ / 128, (B_ * S_) / 128), 256>>>(X, W);
    srcdst_kernel<<<(B_ * S_ * H_) / 8, 256>>>(mask, a);
    attn_kernel<<<dim3(S_ / 128, H_, B_), 128>>>(out);
}

// round 3
// speedup vs baseline: 1.2927x; 1.2927x over previous
#include <cuda_runtime.h>
#include <cuda_bf16.h>

#define B_   8
#define S_   1024
#define IN_  768
#define H_   8
#define F_   64
#define HF_  512
#define BH_  (B_ * H_)
#define ALPHA_ 0.2f

// ---------------------------------------------------------------------------
// Device scratch (no allocations allowed)
// ---------------------------------------------------------------------------
__device__ float  g_Wh[(size_t)B_ * S_ * HF_];            // [row][h*64+f]
__device__ float4 g_ipack[BH_ * S_];                      // (s, exp(s), exp(a*s), 0)
__device__ float4 g_jpack[BH_ * S_];                      // (d, m*exp(d), m*exp(a*d), 0)

__device__ float  g_dsorted[BH_][S_];                     // sorted d per (b,h)
__device__ int    g_perm[BH_][S_];                        // sort permutation
__device__ float  g_e1ds[BH_][S_];                        // m*exp(d) sorted
__device__ float  g_eads[BH_][S_];                        // m*exp(a*d) sorted

// prefix arrays: [bh][k][c], c = 0..63 feature cols, c=64 partition Z, pad to 68
__device__ __align__(16) float g_Pneg[BH_][S_ + 1][68];   // fwd exclusive prefix of eads*Wh
__device__ __align__(16) float g_Ppos[BH_][S_ + 1][68];   // suffix sum of e1ds*Wh

// ---------------------------------------------------------------------------
// K1: Wh = X(8192x768) @ W(768x512), fp32, 128x128 tile, BK=16, 8x8/thread.
// ---------------------------------------------------------------------------
__global__ void __launch_bounds__(256) gemm_wh_kernel(const float* __restrict__ X,
                                                      const float* __restrict__ W)
{
    __shared__ float As[16][132];
    __shared__ float Bs[16][128];

    const int t  = threadIdx.x;
    const int tx = t & 15;
    const int ty = t >> 4;
    const int i0 = blockIdx.y * 128;
    const int f0 = blockIdx.x * 128;

    float acc[8][8];
#pragma unroll
    for (int ii = 0; ii < 8; ii++)
#pragma unroll
        for (int ff = 0; ff < 8; ff++) acc[ii][ff] = 0.f;

    const int ar = t >> 2;
    const int aq = (t & 3) * 4;
    const int br = t >> 5;
    const int bq = (t & 31) * 4;

    for (int k0 = 0; k0 < IN_; k0 += 16) {
        __syncthreads();
        float4 v0 = *(const float4*)(X + (size_t)(i0 + ar) * IN_ + k0 + aq);
        float4 v1 = *(const float4*)(X + (size_t)(i0 + ar + 64) * IN_ + k0 + aq);
        As[aq + 0][ar] = v0.x; As[aq + 1][ar] = v0.y;
        As[aq + 2][ar] = v0.z; As[aq + 3][ar] = v0.w;
        As[aq + 0][ar + 64] = v1.x; As[aq + 1][ar + 64] = v1.y;
        As[aq + 2][ar + 64] = v1.z; As[aq + 3][ar + 64] = v1.w;
        *(float4*)&Bs[br][bq]     = *(const float4*)(W + (size_t)(k0 + br) * HF_ + f0 + bq);
        *(float4*)&Bs[br + 8][bq] = *(const float4*)(W + (size_t)(k0 + br + 8) * HF_ + f0 + bq);
        __syncthreads();

#pragma unroll
        for (int k = 0; k < 16; k++) {
            float a[8], b[8];
            *(float4*)(a)     = *(float4*)&As[k][ty * 8];
            *(float4*)(a + 4) = *(float4*)&As[k][ty * 8 + 4];
            *(float4*)(b)     = *(float4*)&Bs[k][tx * 8];
            *(float4*)(b + 4) = *(float4*)&Bs[k][tx * 8 + 4];
#pragma unroll
            for (int ii = 0; ii < 8; ii++)
#pragma unroll
                for (int ff = 0; ff < 8; ff++)
                    acc[ii][ff] += a[ii] * b[ff];
        }
    }

#pragma unroll
    for (int ii = 0; ii < 8; ii++) {
        float* cp = g_Wh + (size_t)(i0 + ty * 8 + ii) * HF_ + f0 + tx * 8;
        *(float4*)(cp)     = make_float4(acc[ii][0], acc[ii][1], acc[ii][2], acc[ii][3]);
        *(float4*)(cp + 4) = make_float4(acc[ii][4], acc[ii][5], acc[ii][6], acc[ii][7]);
    }
}

// ---------------------------------------------------------------------------
// K2: per (row,h): src/dst dots + exp packing. Warp per task.
// ---------------------------------------------------------------------------
__global__ void __launch_bounds__(256) srcdst_kernel(const int* __restrict__ mask,
                                                     const float* __restrict__ a)
{
    __shared__ float asrc[64], adst[64];
    const int t = threadIdx.x;
    if (t < 64)       asrc[t]      = a[t];
    else if (t < 128) adst[t - 64] = a[t];
    __syncthreads();

    const int lane = t & 31;
    const int task = blockIdx.x * 8 + (t >> 5);
    const int row  = task >> 3;
    const int h    = task & 7;

    float2 v = *(const float2*)(g_Wh + (size_t)row * HF_ + h * F_ + lane * 2);
    float s = v.x * asrc[lane * 2] + v.y * asrc[lane * 2 + 1];
    float d = v.x * adst[lane * 2] + v.y * adst[lane * 2 + 1];
#pragma unroll
    for (int o = 16; o; o >>= 1) {
        s += __shfl_xor_sync(0xffffffffu, s, o);
        d += __shfl_xor_sync(0xffffffffu, d, o);
    }
    if (lane == 0) {
        const int b = row >> 10, i = row & 1023;
        const int idx = (b * H_ + h) * S_ + i;
        g_ipack[idx] = make_float4(s, expf(s), expf(ALPHA_ * s), 0.f);
        const float m = mask[row] ? 1.f : 0.f;
        g_jpack[idx] = make_float4(d, m * expf(d), m * expf(ALPHA_ * d), 0.f);
    }
}

// ---------------------------------------------------------------------------
// K3a: per (b,h): bitonic sort of (d_j, j) ascending. 1024 threads/block.
// ---------------------------------------------------------------------------
__global__ void __launch_bounds__(1024) sort_kernel()
{
    __shared__ float key[S_];
    __shared__ int   pidx[S_];
    const int bh = blockIdx.x;
    const int t  = threadIdx.x;

    key[t]  = g_jpack[bh * S_ + t].x;
    pidx[t] = t;
    __syncthreads();

    for (int k = 2; k <= S_; k <<= 1) {
        for (int j = k >> 1; j > 0; j >>= 1) {
            int ixj = t ^ j;
            if (ixj > t) {
                bool up = ((t & k) == 0);
                float a = key[t], b = key[ixj];
                bool sw = up ? (a > b) : (a < b);
                if (sw) {
                    key[t] = b; key[ixj] = a;
                    int tmp = pidx[t]; pidx[t] = pidx[ixj]; pidx[ixj] = tmp;
                }
            }
            __syncthreads();
        }
    }

    const int p = pidx[t];
    float4 jp = g_jpack[bh * S_ + p];
    g_dsorted[bh][t] = key[t];
    g_perm[bh][t]    = p;
    g_e1ds[bh][t]    = jp.y;
    g_eads[bh][t]    = jp.z;
}

// ---------------------------------------------------------------------------
// K3b: per (bh, dir): column-parallel sequential scan over sorted order.
//   dir 0: Pneg[k][c] = sum_{k'<k} eads[k'] * Wh[perm[k']][c]   (exclusive)
//   dir 1: Ppos[k][c] = sum_{k'>=k} e1ds[k'] * Wh[perm[k']][c]  (suffix)
// Column c = 0..63 feature, c = 64 is Z (weight 1).
// ---------------------------------------------------------------------------
__global__ void __launch_bounds__(128) scan_kernel()
{
    __shared__ int   sp[S_];
    __shared__ float se[S_];
    const int bh  = blockIdx.x;
    const int dir = blockIdx.y;
    const int b = bh >> 3, h = bh & 7;

    for (int q = threadIdx.x; q < S_; q += 128) {
        sp[q] = g_perm[bh][q];
        se[q] = dir ? g_e1ds[bh][q] : g_eads[bh][q];
    }
    __syncthreads();

    const int c = threadIdx.x;
    if (c >= 65) return;

    const float* whb = g_Wh + (size_t)b * S_ * HF_ + h * F_;
    float acc = 0.f;

    if (dir == 0) {
#pragma unroll 8
        for (int k = 0; k < S_; k++) {
            g_Pneg[bh][k][c] = acc;
            float v = se[k];
            if (c < 64) v *= whb[(size_t)sp[k] * HF_ + c];
            acc += v;
        }
        g_Pneg[bh][S_][c] = acc;
    } else {
        g_Ppos[bh][S_][c] = 0.f;
#pragma unroll 8
        for (int k = S_ - 1; k >= 0; k--) {
            float v = se[k];
            if (c < 64) v *= whb[(size_t)sp[k] * HF_ + c];
            acc += v;
            g_Ppos[bh][k][c] = acc;
        }
    }
}

// ---------------------------------------------------------------------------
// K4: epilogue. Block = 16 i-rows x 16 f-quads; binary search split point,
// combine prefix/suffix sums, normalize, write.
// ---------------------------------------------------------------------------
__global__ void __launch_bounds__(256) out_kernel(float* __restrict__ out)
{
    __shared__ float ds[S_];
    const int b = blockIdx.z, h = blockIdx.y;
    const int bh = b * H_ + h;
    const int t = threadIdx.x;

    for (int q = t; q < S_; q += 256) ds[q] = g_dsorted[bh][q];
    __syncthreads();

    const int c4 = t & 15;
    const int il = t >> 4;
    const int i  = blockIdx.x * 16 + il;

    float4 ip = g_ipack[bh * S_ + i];
    const float e1s = ip.y, eas = ip.z;
    const float thr = -ip.x;

    int lo = 0, hi = S_;
    while (lo < hi) {
        int mid = (lo + hi) >> 1;
        if (ds[mid] < thr) lo = mid + 1; else hi = mid;
    }

    const float* pn = &g_Pneg[bh][lo][0];
    const float* pp = &g_Ppos[bh][lo][0];
    float4 n4 = *(const float4*)(pn + c4 * 4);
    float4 p4 = *(const float4*)(pp + c4 * 4);
    const float inv = 1.f / (eas * pn[64] + e1s * pp[64]);

    float4 o;
    o.x = (eas * n4.x + e1s * p4.x) * inv;
    o.y = (eas * n4.y + e1s * p4.y) * inv;
    o.z = (eas * n4.z + e1s * p4.z) * inv;
    o.w = (eas * n4.w + e1s * p4.w) * inv;
    *(float4*)(out + (size_t)(b * S_ + i) * HF_ + h * F_ + c4 * 4) = o;
}

// ---------------------------------------------------------------------------
extern "C" void kernel_launch(void* const* d_in, const int* in_sizes, int n_in,
                              void* d_out, int out_size)
{
    const float* X    = (const float*)d_in[0];
    const int*   mask = (const int*)  d_in[1];
    const float* W    = (const float*)d_in[2];
    const float* a    = (const float*)d_in[3];
    float*       out  = (float*)d_out;

    gemm_wh_kernel<<<dim3(HF_ / 128, (B_ * S_) / 128), 256>>>(X, W);
    srcdst_kernel<<<(B_ * S_ * H_) / 8, 256>>>(mask, a);
    sort_kernel<<<BH_, 1024>>>();
    scan_kernel<<<dim3(BH_, 2), 128>>>();
    out_kernel<<<dim3(S_ / 16, H_, B_), 256>>>(out);
}

// round 4
// speedup vs baseline: 2.5000x; 1.9340x over previous
#include <cuda_runtime.h>
#include <cuda_bf16.h>

#define B_   8
#define S_   1024
#define IN_  768
#define H_   8
#define F_   64
#define HF_  512
#define BH_  (B_ * H_)
#define ALPHA_ 0.2f
#define NCH_  32      // chunks per (b,h)
#define CH_   32      // k's per chunk

// ---------------------------------------------------------------------------
// Device scratch (no allocations allowed)
// ---------------------------------------------------------------------------
__device__ float  g_Wh[(size_t)B_ * S_ * HF_];            // [row][h*64+f]
__device__ float4 g_ipack[BH_ * S_];                      // (s, exp(s), exp(a*s), 0)
__device__ float4 g_jpack[BH_ * S_];                      // (d, m*exp(d), m*exp(a*d), 0)

__device__ float  g_dsorted[BH_][S_];                     // sorted d per (b,h)
__device__ int    g_perm[BH_][S_];                        // sort permutation
__device__ float  g_e1ds[BH_][S_];                        // m*exp(d) sorted
__device__ float  g_eads[BH_][S_];                        // m*exp(a*d) sorted

// Q0[k][c] = exclusive fwd prefix of eads*Wh ; Q1 = exclusive fwd prefix of e1ds*Wh
// c = 0..63 features, c = 64 partition function, padded to 68.
__device__ __align__(16) float g_Q0[BH_][S_ + 1][68];
__device__ __align__(16) float g_Q1[BH_][S_ + 1][68];

// chunk partial sums, scanned in-place into exclusive chunk offsets by scanB
__device__ float g_csum0[BH_][NCH_][68];
__device__ float g_csum1[BH_][NCH_][68];

// ---------------------------------------------------------------------------
// K1: Wh = X(8192x768) @ W(768x512), fp32, 128x128 tile, BK=16, 8x8/thread.
// ---------------------------------------------------------------------------
__global__ void __launch_bounds__(256) gemm_wh_kernel(const float* __restrict__ X,
                                                      const float* __restrict__ W)
{
    __shared__ float As[16][132];
    __shared__ float Bs[16][128];

    const int t  = threadIdx.x;
    const int tx = t & 15;
    const int ty = t >> 4;
    const int i0 = blockIdx.y * 128;
    const int f0 = blockIdx.x * 128;

    float acc[8][8];
#pragma unroll
    for (int ii = 0; ii < 8; ii++)
#pragma unroll
        for (int ff = 0; ff < 8; ff++) acc[ii][ff] = 0.f;

    const int ar = t >> 2;
    const int aq = (t & 3) * 4;
    const int br = t >> 5;
    const int bq = (t & 31) * 4;

    for (int k0 = 0; k0 < IN_; k0 += 16) {
        __syncthreads();
        float4 v0 = *(const float4*)(X + (size_t)(i0 + ar) * IN_ + k0 + aq);
        float4 v1 = *(const float4*)(X + (size_t)(i0 + ar + 64) * IN_ + k0 + aq);
        As[aq + 0][ar] = v0.x; As[aq + 1][ar] = v0.y;
        As[aq + 2][ar] = v0.z; As[aq + 3][ar] = v0.w;
        As[aq + 0][ar + 64] = v1.x; As[aq + 1][ar + 64] = v1.y;
        As[aq + 2][ar + 64] = v1.z; As[aq + 3][ar + 64] = v1.w;
        *(float4*)&Bs[br][bq]     = *(const float4*)(W + (size_t)(k0 + br) * HF_ + f0 + bq);
        *(float4*)&Bs[br + 8][bq] = *(const float4*)(W + (size_t)(k0 + br + 8) * HF_ + f0 + bq);
        __syncthreads();

#pragma unroll
        for (int k = 0; k < 16; k++) {
            float a[8], b[8];
            *(float4*)(a)     = *(float4*)&As[k][ty * 8];
            *(float4*)(a + 4) = *(float4*)&As[k][ty * 8 + 4];
            *(float4*)(b)     = *(float4*)&Bs[k][tx * 8];
            *(float4*)(b + 4) = *(float4*)&Bs[k][tx * 8 + 4];
#pragma unroll
            for (int ii = 0; ii < 8; ii++)
#pragma unroll
                for (int ff = 0; ff < 8; ff++)
                    acc[ii][ff] += a[ii] * b[ff];
        }
    }

#pragma unroll
    for (int ii = 0; ii < 8; ii++) {
        float* cp = g_Wh + (size_t)(i0 + ty * 8 + ii) * HF_ + f0 + tx * 8;
        *(float4*)(cp)     = make_float4(acc[ii][0], acc[ii][1], acc[ii][2], acc[ii][3]);
        *(float4*)(cp + 4) = make_float4(acc[ii][4], acc[ii][5], acc[ii][6], acc[ii][7]);
    }
}

// ---------------------------------------------------------------------------
// K2: per (row,h): src/dst dots + exp packing. Warp per task.
// ---------------------------------------------------------------------------
__global__ void __launch_bounds__(256) srcdst_kernel(const int* __restrict__ mask,
                                                     const float* __restrict__ a)
{
    __shared__ float asrc[64], adst[64];
    const int t = threadIdx.x;
    if (t < 64)       asrc[t]      = a[t];
    else if (t < 128) adst[t - 64] = a[t];
    __syncthreads();

    const int lane = t & 31;
    const int task = blockIdx.x * 8 + (t >> 5);
    const int row  = task >> 3;
    const int h    = task & 7;

    float2 v = *(const float2*)(g_Wh + (size_t)row * HF_ + h * F_ + lane * 2);
    float s = v.x * asrc[lane * 2] + v.y * asrc[lane * 2 + 1];
    float d = v.x * adst[lane * 2] + v.y * adst[lane * 2 + 1];
#pragma unroll
    for (int o = 16; o; o >>= 1) {
        s += __shfl_xor_sync(0xffffffffu, s, o);
        d += __shfl_xor_sync(0xffffffffu, d, o);
    }
    if (lane == 0) {
        const int b = row >> 10, i = row & 1023;
        const int idx = (b * H_ + h) * S_ + i;
        g_ipack[idx] = make_float4(s, expf(s), expf(ALPHA_ * s), 0.f);
        const float m = mask[row] ? 1.f : 0.f;
        g_jpack[idx] = make_float4(d, m * expf(d), m * expf(ALPHA_ * d), 0.f);
    }
}

// ---------------------------------------------------------------------------
// K3a: per (b,h): bitonic sort of (d_j, j) ascending. 1024 threads/block.
// ---------------------------------------------------------------------------
__global__ void __launch_bounds__(1024) sort_kernel()
{
    __shared__ float key[S_];
    __shared__ int   pidx[S_];
    const int bh = blockIdx.x;
    const int t  = threadIdx.x;

    key[t]  = g_jpack[bh * S_ + t].x;
    pidx[t] = t;
    __syncthreads();

    for (int k = 2; k <= S_; k <<= 1) {
        for (int j = k >> 1; j > 0; j >>= 1) {
            int ixj = t ^ j;
            if (ixj > t) {
                bool up = ((t & k) == 0);
                float a = key[t], b = key[ixj];
                bool sw = up ? (a > b) : (a < b);
                if (sw) {
                    key[t] = b; key[ixj] = a;
                    int tmp = pidx[t]; pidx[t] = pidx[ixj]; pidx[ixj] = tmp;
                }
            }
            __syncthreads();
        }
    }

    const int p = pidx[t];
    float4 jp = g_jpack[bh * S_ + p];
    g_dsorted[bh][t] = key[t];
    g_perm[bh][t]    = p;
    g_e1ds[bh][t]    = jp.y;
    g_eads[bh][t]    = jp.z;
}

// ---------------------------------------------------------------------------
// K3b-A: chunk partial sums. Block = (bh, chunk), 96 threads (c < 65 active).
//   csum0[c] = sum_{k in chunk} eads[k] * Wh[perm[k]][c]   (c=64: v=1)
//   csum1[c] = sum_{k in chunk} e1ds[k] * Wh[perm[k]][c]
// ---------------------------------------------------------------------------
__global__ void __launch_bounds__(96) scanA_kernel()
{
    __shared__ int   sp[CH_];
    __shared__ float sw0[CH_], sw1[CH_];
    const int bh = blockIdx.x;
    const int ch = blockIdx.y;
    const int b = bh >> 3, h = bh & 7;
    const int t = threadIdx.x;

    if (t < CH_) {
        const int kk = ch * CH_ + t;
        sp[t]  = g_perm[bh][kk] * HF_;
        sw0[t] = g_eads[bh][kk];
        sw1[t] = g_e1ds[bh][kk];
    }
    __syncthreads();
    if (t >= 65) return;

    const float* __restrict__ whb = g_Wh + (size_t)b * S_ * HF_ + h * F_ + t;
    const bool feat = (t < 64);
    float s0 = 0.f, s1 = 0.f;
#pragma unroll
    for (int k = 0; k < CH_; k++) {
        const float v = feat ? __ldg(whb + sp[k]) : 1.f;
        s0 += sw0[k] * v;
        s1 += sw1[k] * v;
    }
    g_csum0[bh][ch][t] = s0;
    g_csum1[bh][ch][t] = s1;
}

// ---------------------------------------------------------------------------
// K3b-B: per (bh, c): exclusive scan of the 32 chunk sums, in place.
// ---------------------------------------------------------------------------
__global__ void __launch_bounds__(96) scanB_kernel()
{
    const int bh = blockIdx.x;
    const int c  = threadIdx.x;
    if (c >= 65) return;

    float v0[NCH_], v1[NCH_];
#pragma unroll
    for (int ch = 0; ch < NCH_; ch++) {
        v0[ch] = g_csum0[bh][ch][c];
        v1[ch] = g_csum1[bh][ch][c];
    }
    float a0 = 0.f, a1 = 0.f;
#pragma unroll
    for (int ch = 0; ch < NCH_; ch++) {
        const float t0 = v0[ch], t1 = v1[ch];
        g_csum0[bh][ch][c] = a0;
        g_csum1[bh][ch][c] = a1;
        a0 += t0; a1 += t1;
    }
}

// ---------------------------------------------------------------------------
// K3b-C: materialize Q0/Q1 exclusive prefixes. Block = (bh, chunk), 96 thr.
// Chunk 31 additionally writes the totals row Q[S_].
// ---------------------------------------------------------------------------
__global__ void __launch_bounds__(96) scanC_kernel()
{
    __shared__ int   sp[CH_];
    __shared__ float sw0[CH_], sw1[CH_];
    const int bh = blockIdx.x;
    const int ch = blockIdx.y;
    const int b = bh >> 3, h = bh & 7;
    const int t = threadIdx.x;

    if (t < CH_) {
        const int kk = ch * CH_ + t;
        sp[t]  = g_perm[bh][kk] * HF_;
        sw0[t] = g_eads[bh][kk];
        sw1[t] = g_e1ds[bh][kk];
    }
    __syncthreads();
    if (t >= 65) return;

    const float* __restrict__ whb = g_Wh + (size_t)b * S_ * HF_ + h * F_ + t;
    const bool feat = (t < 64);
    const int k0 = ch * CH_;

    float off0 = g_csum0[bh][ch][t];
    float off1 = g_csum1[bh][ch][t];
#pragma unroll
    for (int k = 0; k < CH_; k++) {
        g_Q0[bh][k0 + k][t] = off0;
        g_Q1[bh][k0 + k][t] = off1;
        const float v = feat ? __ldg(whb + sp[k]) : 1.f;
        off0 += sw0[k] * v;
        off1 += sw1[k] * v;
    }
    if (ch == NCH_ - 1) {
        g_Q0[bh][S_][t] = off0;
        g_Q1[bh][S_][t] = off1;
    }
}

// ---------------------------------------------------------------------------
// K4: epilogue. Binary search split point; combine:
//   out = (eas*Q0[lo] + e1s*(Q1[S]-Q1[lo])) / (eas*Q0z[lo] + e1s*(Q1z[S]-Q1z[lo]))
// ---------------------------------------------------------------------------
__global__ void __launch_bounds__(256) out_kernel(float* __restrict__ out)
{
    __shared__ float ds[S_];
    const int b = blockIdx.z, h = blockIdx.y;
    const int bh = b * H_ + h;
    const int t = threadIdx.x;

    for (int q = t; q < S_; q += 256) ds[q] = g_dsorted[bh][q];
    __syncthreads();

    const int c4 = t & 15;
    const int il = t >> 4;
    const int i  = blockIdx.x * 16 + il;

    float4 ip = g_ipack[bh * S_ + i];
    const float e1s = ip.y, eas = ip.z;
    const float thr = -ip.x;

    int lo = 0, hi = S_;
    while (lo < hi) {
        int mid = (lo + hi) >> 1;
        if (ds[mid] < thr) lo = mid + 1; else hi = mid;
    }

    const float* q0 = &g_Q0[bh][lo][0];
    const float* q1 = &g_Q1[bh][lo][0];
    const float* t1 = &g_Q1[bh][S_][0];

    float4 n4 = *(const float4*)(q0 + c4 * 4);
    float4 q4 = *(const float4*)(q1 + c4 * 4);
    float4 t4 = *(const float4*)(t1 + c4 * 4);
    const float zpos = t1[64] - q1[64];
    const float inv = 1.f / (eas * q0[64] + e1s * zpos);

    float4 o;
    o.x = (eas * n4.x + e1s * (t4.x - q4.x)) * inv;
    o.y = (eas * n4.y + e1s * (t4.y - q4.y)) * inv;
    o.z = (eas * n4.z + e1s * (t4.z - q4.z)) * inv;
    o.w = (eas * n4.w + e1s * (t4.w - q4.w)) * inv;
    *(float4*)(out + (size_t)(b * S_ + i) * HF_ + h * F_ + c4 * 4) = o;
}

// ---------------------------------------------------------------------------
extern "C" void kernel_launch(void* const* d_in, const int* in_sizes, int n_in,
                              void* d_out, int out_size)
{
    const float* X    = (const float*)d_in[0];
    const int*   mask = (const int*)  d_in[1];
    const float* W    = (const float*)d_in[2];
    const float* a    = (const float*)d_in[3];
    float*       out  = (float*)d_out;

    gemm_wh_kernel<<<dim3(HF_ / 128, (B_ * S_) / 128), 256>>>(X, W);
    srcdst_kernel<<<(B_ * S_ * H_) / 8, 256>>>(mask, a);
    sort_kernel<<<BH_, 1024>>>();
    scanA_kernel<<<dim3(BH_, NCH_), 96>>>();
    scanB_kernel<<<BH_, 96>>>();
    scanC_kernel<<<dim3(BH_, NCH_), 96>>>();
    out_kernel<<<dim3(S_ / 16, H_, B_), 256>>>(out);
}

// round 8
// speedup vs baseline: 2.5477x; 1.0191x over previous
#include <cuda_runtime.h>
#include <cuda_bf16.h>
#include <cstdint>

#define B_   8
#define S_   1024
#define IN_  768
#define H_   8
#define F_   64
#define HF_  512
#define BH_  (B_ * H_)
#define ALPHA_ 0.2f
#define NCH_  32      // scan chunks per (b,h)
#define CH_   32      // k's per scan chunk

// ---------------------------------------------------------------------------
// Device scratch (no allocations allowed)
// ---------------------------------------------------------------------------
__device__ float  g_Wh[(size_t)B_ * S_ * HF_];            // [row][h*64+f]
__device__ float4 g_ipack[BH_ * S_];                      // (s, exp(s), exp(a*s), 0)
__device__ float4 g_jpack[BH_ * S_];                      // (d, m*exp(d), m*exp(a*d), 0)

__device__ float  g_dsorted[BH_][S_];
__device__ int    g_perm[BH_][S_];
__device__ float  g_e1ds[BH_][S_];
__device__ float  g_eads[BH_][S_];

__device__ __align__(16) float g_Q0[BH_][S_ + 1][68];
__device__ __align__(16) float g_Q1[BH_][S_ + 1][68];
__device__ float g_csum0[BH_][NCH_][68];
__device__ float g_csum1[BH_][NCH_][68];

// ---------------------------------------------------------------------------
// Packed f32x2 helpers (Blackwell base ISA, works on family target sm_103)
// ---------------------------------------------------------------------------
#define FMA_F32X2(d, a, b) \
    asm("fma.rn.f32x2 %0, %1, %2, %3;" : "=l"(d) : "l"(a), "l"(b), "l"(d))
#define PACK_BCAST(d, x) \
    asm("mov.b64 %0, {%1, %1};" : "=l"(d) : "r"(x))

// ---------------------------------------------------------------------------
// K1: Wh = X(8192x768) @ W(768x512), fp32 via packed f32x2 FMA.
// 128x128 tile, BK=16, 8x8 per thread (as 8x4 f32x2 pairs).
// ---------------------------------------------------------------------------
__global__ void __launch_bounds__(256) gemm_wh_kernel(const float* __restrict__ X,
                                                      const float* __restrict__ W)
{
    __shared__ float As[16][132];   // transposed A tile (+4 pad)
    __shared__ float Bs[16][128];

    const int t  = threadIdx.x;
    const int tx = t & 15;          // f-group: f = tx*8
    const int ty = t >> 4;          // i-group: i = ty*8
    const int i0 = blockIdx.y * 128;
    const int f0 = blockIdx.x * 128;

    unsigned long long acc2[8][4];  // [ii][f-pair] packed (f0,f1) fp32 pairs
#pragma unroll
    for (int ii = 0; ii < 8; ii++)
#pragma unroll
        for (int fp = 0; fp < 4; fp++) acc2[ii][fp] = 0ull;

    const int ar = t >> 2;
    const int aq = (t & 3) * 4;
    const int br = t >> 5;
    const int bq = (t & 31) * 4;

    for (int k0 = 0; k0 < IN_; k0 += 16) {
        __syncthreads();
        float4 v0 = *(const float4*)(X + (size_t)(i0 + ar) * IN_ + k0 + aq);
        float4 v1 = *(const float4*)(X + (size_t)(i0 + ar + 64) * IN_ + k0 + aq);
        As[aq + 0][ar] = v0.x; As[aq + 1][ar] = v0.y;
        As[aq + 2][ar] = v0.z; As[aq + 3][ar] = v0.w;
        As[aq + 0][ar + 64] = v1.x; As[aq + 1][ar + 64] = v1.y;
        As[aq + 2][ar + 64] = v1.z; As[aq + 3][ar + 64] = v1.w;
        *(float4*)&Bs[br][bq]     = *(const float4*)(W + (size_t)(k0 + br) * HF_ + f0 + bq);
        *(float4*)&Bs[br + 8][bq] = *(const float4*)(W + (size_t)(k0 + br + 8) * HF_ + f0 + bq);
        __syncthreads();

#pragma unroll
        for (int k = 0; k < 16; k++) {
            // b operands: 8 floats = 4 packed pairs, loaded as two 16B LDS
            ulonglong2 blo = *(ulonglong2*)&Bs[k][tx * 8];
            ulonglong2 bhi = *(ulonglong2*)&Bs[k][tx * 8 + 4];
            unsigned long long bp[4] = { blo.x, blo.y, bhi.x, bhi.y };
            float a[8];
            *(float4*)(a)     = *(float4*)&As[k][ty * 8];
            *(float4*)(a + 4) = *(float4*)&As[k][ty * 8 + 4];
#pragma unroll
            for (int ii = 0; ii < 8; ii++) {
                unsigned long long ap;
                PACK_BCAST(ap, __float_as_uint(a[ii]));
#pragma unroll
                for (int fp = 0; fp < 4; fp++)
                    FMA_F32X2(acc2[ii][fp], ap, bp[fp]);
            }
        }
    }

#pragma unroll
    for (int ii = 0; ii < 8; ii++) {
        float* cp = g_Wh + (size_t)(i0 + ty * 8 + ii) * HF_ + f0 + tx * 8;
        float2 p0 = *(float2*)&acc2[ii][0];
        float2 p1 = *(float2*)&acc2[ii][1];
        float2 p2 = *(float2*)&acc2[ii][2];
        float2 p3 = *(float2*)&acc2[ii][3];
        *(float4*)(cp)     = make_float4(p0.x, p0.y, p1.x, p1.y);
        *(float4*)(cp + 4) = make_float4(p2.x, p2.y, p3.x, p3.y);
    }
}

// ---------------------------------------------------------------------------
// K2: per (row,h): src/dst dots + exp packing. Warp per task.
// ---------------------------------------------------------------------------
__global__ void __launch_bounds__(256) srcdst_kernel(const int* __restrict__ mask,
                                                     const float* __restrict__ a)
{
    __shared__ float asrc[64], adst[64];
    const int t = threadIdx.x;
    if (t < 64)       asrc[t]      = a[t];
    else if (t < 128) adst[t - 64] = a[t];
    __syncthreads();

    const int lane = t & 31;
    const int task = blockIdx.x * 8 + (t >> 5);
    const int row  = task >> 3;
    const int h    = task & 7;

    float2 v = *(const float2*)(g_Wh + (size_t)row * HF_ + h * F_ + lane * 2);
    float s = v.x * asrc[lane * 2] + v.y * asrc[lane * 2 + 1];
    float d = v.x * adst[lane * 2] + v.y * adst[lane * 2 + 1];
#pragma unroll
    for (int o = 16; o; o >>= 1) {
        s += __shfl_xor_sync(0xffffffffu, s, o);
        d += __shfl_xor_sync(0xffffffffu, d, o);
    }
    if (lane == 0) {
        const int b = row >> 10, i = row & 1023;
        const int idx = (b * H_ + h) * S_ + i;
        g_ipack[idx] = make_float4(s, expf(s), expf(ALPHA_ * s), 0.f);
        const float m = mask[row] ? 1.f : 0.f;
        g_jpack[idx] = make_float4(d, m * expf(d), m * expf(ALPHA_ * d), 0.f);
    }
}

// ---------------------------------------------------------------------------
// K3a: per (b,h): bitonic sort of (d_j, j) ascending. 1024 threads/block.
// ---------------------------------------------------------------------------
__global__ void __launch_bounds__(1024) sort_kernel()
{
    __shared__ float key[S_];
    __shared__ int   pidx[S_];
    const int bh = blockIdx.x;
    const int t  = threadIdx.x;

    key[t]  = g_jpack[bh * S_ + t].x;
    pidx[t] = t;
    __syncthreads();

    for (int k = 2; k <= S_; k <<= 1) {
        for (int j = k >> 1; j > 0; j >>= 1) {
            int ixj = t ^ j;
            if (ixj > t) {
                bool up = ((t & k) == 0);
                float a = key[t], b = key[ixj];
                bool sw = up ? (a > b) : (a < b);
                if (sw) {
                    key[t] = b; key[ixj] = a;
                    int tmp = pidx[t]; pidx[t] = pidx[ixj]; pidx[ixj] = tmp;
                }
            }
            __syncthreads();
        }
    }

    const int p = pidx[t];
    float4 jp = g_jpack[bh * S_ + p];
    g_dsorted[bh][t] = key[t];
    g_perm[bh][t]    = p;
    g_e1ds[bh][t]    = jp.y;
    g_eads[bh][t]    = jp.z;
}

// ---------------------------------------------------------------------------
// K3b-A: chunk partial sums. Block = (bh, chunk), 96 threads (c < 65 active).
// ---------------------------------------------------------------------------
__global__ void __launch_bounds__(96) scanA_kernel()
{
    __shared__ int   sp[CH_];
    __shared__ float sw0[CH_], sw1[CH_];
    const int bh = blockIdx.x;
    const int ch = blockIdx.y;
    const int b = bh >> 3, h = bh & 7;
    const int t = threadIdx.x;

    if (t < CH_) {
        const int kk = ch * CH_ + t;
        sp[t]  = g_perm[bh][kk] * HF_;
        sw0[t] = g_eads[bh][kk];
        sw1[t] = g_e1ds[bh][kk];
    }
    __syncthreads();
    if (t >= 65) return;

    const float* __restrict__ whb = g_Wh + (size_t)b * S_ * HF_ + h * F_ + t;
    const bool feat = (t < 64);
    float s0 = 0.f, s1 = 0.f;
#pragma unroll
    for (int k = 0; k < CH_; k++) {
        const float v = feat ? __ldg(whb + sp[k]) : 1.f;
        s0 += sw0[k] * v;
        s1 += sw1[k] * v;
    }
    g_csum0[bh][ch][t] = s0;
    g_csum1[bh][ch][t] = s1;
}

// ---------------------------------------------------------------------------
// K3b-B: per (bh, c): exclusive scan of the 32 chunk sums, in place.
// ---------------------------------------------------------------------------
__global__ void __launch_bounds__(96) scanB_kernel()
{
    const int bh = blockIdx.x;
    const int c  = threadIdx.x;
    if (c >= 65) return;

    float v0[NCH_], v1[NCH_];
#pragma unroll
    for (int ch = 0; ch < NCH_; ch++) {
        v0[ch] = g_csum0[bh][ch][c];
        v1[ch] = g_csum1[bh][ch][c];
    }
    float a0 = 0.f, a1 = 0.f;
#pragma unroll
    for (int ch = 0; ch < NCH_; ch++) {
        const float t0 = v0[ch], t1 = v1[ch];
        g_csum0[bh][ch][c] = a0;
        g_csum1[bh][ch][c] = a1;
        a0 += t0; a1 += t1;
    }
}

// ---------------------------------------------------------------------------
// K3b-C: materialize Q0/Q1 exclusive prefixes. Block = (bh, chunk), 96 thr.
// ---------------------------------------------------------------------------
__global__ void __launch_bounds__(96) scanC_kernel()
{
    __shared__ int   sp[CH_];
    __shared__ float sw0[CH_], sw1[CH_];
    const int bh = blockIdx.x;
    const int ch = blockIdx.y;
    const int b = bh >> 3, h = bh & 7;
    const int t = threadIdx.x;

    if (t < CH_) {
        const int kk = ch * CH_ + t;
        sp[t]  = g_perm[bh][kk] * HF_;
        sw0[t] = g_eads[bh][kk];
        sw1[t] = g_e1ds[bh][kk];
    }
    __syncthreads();
    if (t >= 65) return;

    const float* __restrict__ whb = g_Wh + (size_t)b * S_ * HF_ + h * F_ + t;
    const bool feat = (t < 64);
    const int k0 = ch * CH_;

    float off0 = g_csum0[bh][ch][t];
    float off1 = g_csum1[bh][ch][t];
#pragma unroll
    for (int k = 0; k < CH_; k++) {
        g_Q0[bh][k0 + k][t] = off0;
        g_Q1[bh][k0 + k][t] = off1;
        const float v = feat ? __ldg(whb + sp[k]) : 1.f;
        off0 += sw0[k] * v;
        off1 += sw1[k] * v;
    }
    if (ch == NCH_ - 1) {
        g_Q0[bh][S_][t] = off0;
        g_Q1[bh][S_][t] = off1;
    }
}

// ---------------------------------------------------------------------------
// K4: epilogue. Binary search split point; combine prefix/suffix; normalize.
// ---------------------------------------------------------------------------
__global__ void __launch_bounds__(256) out_kernel(float* __restrict__ out)
{
    __shared__ float ds[S_];
    const int b = blockIdx.z, h = blockIdx.y;
    const int bh = b * H_ + h;
    const int t = threadIdx.x;

    for (int q = t; q < S_; q += 256) ds[q] = g_dsorted[bh][q];
    __syncthreads();

    const int c4 = t & 15;
    const int il = t >> 4;
    const int i  = blockIdx.x * 16 + il;

    float4 ip = g_ipack[bh * S_ + i];
    const float e1s = ip.y, eas = ip.z;
    const float thr = -ip.x;

    int lo = 0, hi = S_;
    while (lo < hi) {
        int mid = (lo + hi) >> 1;
        if (ds[mid] < thr) lo = mid + 1; else hi = mid;
    }

    const float* q0 = &g_Q0[bh][lo][0];
    const float* q1 = &g_Q1[bh][lo][0];
    const float* t1 = &g_Q1[bh][S_][0];

    float4 n4 = *(const float4*)(q0 + c4 * 4);
    float4 q4 = *(const float4*)(q1 + c4 * 4);
    float4 t4 = *(const float4*)(t1 + c4 * 4);
    const float zpos = t1[64] - q1[64];
    const float inv = 1.f / (eas * q0[64] + e1s * zpos);

    float4 o;
    o.x = (eas * n4.x + e1s * (t4.x - q4.x)) * inv;
    o.y = (eas * n4.y + e1s * (t4.y - q4.y)) * inv;
    o.z = (eas * n4.z + e1s * (t4.z - q4.z)) * inv;
    o.w = (eas * n4.w + e1s * (t4.w - q4.w)) * inv;
    *(float4*)(out + (size_t)(b * S_ + i) * HF_ + h * F_ + c4 * 4) = o;
}

// ---------------------------------------------------------------------------
extern "C" void kernel_launch(void* const* d_in, const int* in_sizes, int n_in,
                              void* d_out, int out_size)
{
    const float* X    = (const float*)d_in[0];
    const int*   mask = (const int*)  d_in[1];
    const float* W    = (const float*)d_in[2];
    const float* a    = (const float*)d_in[3];
    float*       out  = (float*)d_out;

    gemm_wh_kernel<<<dim3(HF_ / 128, (B_ * S_) / 128), 256>>>(X, W);
    srcdst_kernel<<<(B_ * S_ * H_) / 8, 256>>>(mask, a);
    sort_kernel<<<BH_, 1024>>>();
    scanA_kernel<<<dim3(BH_, NCH_), 96>>>();
    scanB_kernel<<<BH_, 96>>>();
    scanC_kernel<<<dim3(BH_, NCH_), 96>>>();
    out_kernel<<<dim3(S_ / 16, H_, B_), 256>>>(out);
}

// round 9
// speedup vs baseline: 3.8287x; 1.5028x over previous
#include <cuda_runtime.h>
#include <cuda_bf16.h>
#include <cstdint>

#define B_   8
#define S_   1024
#define IN_  768
#define H_   8
#define F_   64
#define HF_  512
#define BH_  (B_ * H_)
#define ALPHA_ 0.2f
#define NCH_  32
#define CH_   32

// ---------------------------------------------------------------------------
// Device scratch (no allocations allowed)
// ---------------------------------------------------------------------------
__device__ float  g_Wh[(size_t)B_ * S_ * HF_];
__device__ __nv_bfloat16 g_Xhi[(size_t)B_ * S_ * IN_];
__device__ __nv_bfloat16 g_Xlo[(size_t)B_ * S_ * IN_];
__device__ __nv_bfloat16 g_Wth[(size_t)HF_ * IN_];   // W^T [n][k] hi
__device__ __nv_bfloat16 g_Wtl[(size_t)HF_ * IN_];   // lo

__device__ float4 g_ipack[BH_ * S_];
__device__ float4 g_jpack[BH_ * S_];

__device__ float  g_dsorted[BH_][S_];
__device__ int    g_perm[BH_][S_];
__device__ float  g_e1ds[BH_][S_];
__device__ float  g_eads[BH_][S_];

__device__ __align__(16) float g_Q0[BH_][S_ + 1][68];
__device__ __align__(16) float g_Q1[BH_][S_ + 1][68];
__device__ float g_csum0[BH_][NCH_][68];
__device__ float g_csum1[BH_][NCH_][68];

// ---------------------------------------------------------------------------
// PTX helpers (all baseline sm_80+ features: valid on family target sm_103)
// ---------------------------------------------------------------------------
__device__ __forceinline__ uint32_t smem_u32(const void* p) {
    uint32_t a;
    asm("{ .reg .u64 t; cvta.to.shared.u64 t, %1; cvt.u32.u64 %0, t; }"
        : "=r"(a) : "l"(p));
    return a;
}
__device__ __forceinline__ unsigned long long gmem_u64(const void* p) {
    unsigned long long a;
    asm("cvta.to.global.u64 %0, %1;" : "=l"(a) : "l"(p));
    return a;
}
#define CP_ASYNC16(s, g) \
    asm volatile("cp.async.cg.shared.global [%0], [%1], 16;" :: "r"(s), "l"(g) : "memory")
#define CP_COMMIT() asm volatile("cp.async.commit_group;" ::: "memory")
#define CP_WAIT0()  asm volatile("cp.async.wait_group 0;" ::: "memory")

#define LDX4(r, addr) \
    asm volatile("ldmatrix.sync.aligned.m8n8.x4.shared.b16 {%0,%1,%2,%3}, [%4];" \
                 : "=r"((r)[0]), "=r"((r)[1]), "=r"((r)[2]), "=r"((r)[3]) : "r"(addr))

#define MMA_BF16(cc, a, b0, b1) \
    asm volatile("mma.sync.aligned.m16n8k16.row.col.f32.bf16.bf16.f32 " \
                 "{%0,%1,%2,%3}, {%4,%5,%6,%7}, {%8,%9}, {%0,%1,%2,%3};" \
                 : "+f"((cc)[0]), "+f"((cc)[1]), "+f"((cc)[2]), "+f"((cc)[3]) \
                 : "r"((a)[0]), "r"((a)[1]), "r"((a)[2]), "r"((a)[3]), "r"(b0), "r"(b1))

// ---------------------------------------------------------------------------
// K0a: split X into bf16 hi/lo
// ---------------------------------------------------------------------------
__global__ void __launch_bounds__(256) convX_kernel(const float* __restrict__ X)
{
    const size_t i = ((size_t)blockIdx.x * 256 + threadIdx.x) * 4;
    float4 v = *(const float4*)(X + i);
    __nv_bfloat16 h0 = __float2bfloat16(v.x), h1 = __float2bfloat16(v.y);
    __nv_bfloat16 h2 = __float2bfloat16(v.z), h3 = __float2bfloat16(v.w);
    __nv_bfloat16 l0 = __float2bfloat16(v.x - __bfloat162float(h0));
    __nv_bfloat16 l1 = __float2bfloat16(v.y - __bfloat162float(h1));
    __nv_bfloat16 l2 = __float2bfloat16(v.z - __bfloat162float(h2));
    __nv_bfloat16 l3 = __float2bfloat16(v.w - __bfloat162float(h3));
    *(__nv_bfloat162*)(g_Xhi + i)     = __nv_bfloat162(h0, h1);
    *(__nv_bfloat162*)(g_Xhi + i + 2) = __nv_bfloat162(h2, h3);
    *(__nv_bfloat162*)(g_Xlo + i)     = __nv_bfloat162(l0, l1);
    *(__nv_bfloat162*)(g_Xlo + i + 2) = __nv_bfloat162(l2, l3);
}

// ---------------------------------------------------------------------------
// K0b: transpose + split W -> Wt[n][k] hi/lo  (768x512 -> 512x768)
// ---------------------------------------------------------------------------
__global__ void __launch_bounds__(256) convW_kernel(const float* __restrict__ W)
{
    __shared__ float tile[32][33];
    const int kb = blockIdx.x * 32;
    const int nb = blockIdx.y * 32;
    const int tx = threadIdx.x & 31, ty = threadIdx.x >> 5;
#pragma unroll
    for (int r = ty; r < 32; r += 8)
        tile[r][tx] = W[(size_t)(kb + r) * HF_ + nb + tx];
    __syncthreads();
#pragma unroll
    for (int r = ty; r < 32; r += 8) {
        float x = tile[tx][r];
        __nv_bfloat16 h = __float2bfloat16(x);
        g_Wth[(size_t)(nb + r) * IN_ + kb + tx] = h;
        g_Wtl[(size_t)(nb + r) * IN_ + kb + tx] = __float2bfloat16(x - __bfloat162float(h));
    }
}

// ---------------------------------------------------------------------------
// K1: split-bf16 tensor-core GEMM via mma.sync (baseline HMMA path).
// CTA 128x128, 8 warps (4M x 2N), warp tile 32x64, BK=32, double-buffered
// cp.async. Wh = Xhi*Whi + Xhi*Wlo + Xlo*Whi, fp32 accum.
// SMEM stage: Ahi | Alo | Bhi | Blo, each 128 rows x 32 bf16, row stride 80B.
// ---------------------------------------------------------------------------
#define STG_    40960
#define AHI_    0
#define ALO_    10240
#define BHI_    20480
#define BLO_    30720
#define NSTAGE_ (IN_ / 32)   // 24

__global__ void __launch_bounds__(256) mma_gemm_kernel()
{
    extern __shared__ __align__(16) char smem[];
    const int t = threadIdx.x;
    const int wid = t >> 5;
    const int lane = t & 31;
    const int warp_m = wid >> 1;        // 0..3
    const int warp_n = wid & 1;         // 0..1
    const int i0 = blockIdx.x * 128;
    const int f0 = blockIdx.y * 128;
    const uint32_t sb0 = smem_u32(smem);

    float acc[2][8][4];
#pragma unroll
    for (int mt = 0; mt < 2; mt++)
#pragma unroll
        for (int nt = 0; nt < 8; nt++)
#pragma unroll
            for (int q = 0; q < 4; q++) acc[mt][nt][q] = 0.f;

    // stage loader: 2048 16B pieces / 256 threads = 8 cp.async per thread
    auto load_stage = [&](int ch, int s) {
        const uint32_t st = sb0 + s * STG_;
        const int k0 = ch * 32;
#pragma unroll
        for (int p = t; p < 512; p += 256) {
            const int row = p >> 2, q = p & 3;
            const uint32_t so = st + row * 80 + q * 16;
            const size_t ga = (size_t)(i0 + row) * IN_ + k0 + q * 8;
            const size_t gb = (size_t)(f0 + row) * IN_ + k0 + q * 8;
            CP_ASYNC16(so + AHI_, gmem_u64(g_Xhi + ga));
            CP_ASYNC16(so + ALO_, gmem_u64(g_Xlo + ga));
            CP_ASYNC16(so + BHI_, gmem_u64(g_Wth + gb));
            CP_ASYNC16(so + BLO_, gmem_u64(g_Wtl + gb));
        }
        CP_COMMIT();
    };

    load_stage(0, 0);

    const uint32_t a_lane_off = (lane & 15) * 80 + (lane >> 4) * 16;

    for (int ch = 0; ch < NSTAGE_; ch++) {
        CP_WAIT0();
        __syncthreads();
        if (ch + 1 < NSTAGE_) load_stage(ch + 1, (ch + 1) & 1);

        const uint32_t st = sb0 + (ch & 1) * STG_;
#pragma unroll
        for (int kt = 0; kt < 2; kt++) {
            uint32_t ah[2][4], al[2][4];
#pragma unroll
            for (int mt = 0; mt < 2; mt++) {
                const uint32_t aa = st + AHI_ + (warp_m * 32 + mt * 16) * 80
                                  + kt * 32 + a_lane_off;
                LDX4(ah[mt], aa);
                LDX4(al[mt], aa + (ALO_ - AHI_));
            }
#pragma unroll
            for (int nt = 0; nt < 4; nt++) {
                uint32_t bh[4], bl[4];
                const uint32_t ba = st + BHI_ + (warp_n * 64 + nt * 16) * 80
                                  + kt * 32 + a_lane_off;
                LDX4(bh, ba);
                LDX4(bl, ba + (BLO_ - BHI_));
#pragma unroll
                for (int mt = 0; mt < 2; mt++) {
                    MMA_BF16(acc[mt][nt * 2],     ah[mt], bh[0], bh[2]);
                    MMA_BF16(acc[mt][nt * 2],     al[mt], bh[0], bh[2]);
                    MMA_BF16(acc[mt][nt * 2],     ah[mt], bl[0], bl[2]);
                    MMA_BF16(acc[mt][nt * 2 + 1], ah[mt], bh[1], bh[3]);
                    MMA_BF16(acc[mt][nt * 2 + 1], al[mt], bh[1], bh[3]);
                    MMA_BF16(acc[mt][nt * 2 + 1], ah[mt], bl[1], bl[3]);
                }
            }
        }
        __syncthreads();
    }

    // epilogue: acc -> g_Wh
#pragma unroll
    for (int mt = 0; mt < 2; mt++) {
        const int r0 = i0 + warp_m * 32 + mt * 16 + (lane >> 2);
#pragma unroll
        for (int nt = 0; nt < 8; nt++) {
            const int c = f0 + warp_n * 64 + nt * 8 + (lane & 3) * 2;
            *(float2*)(g_Wh + (size_t)r0 * HF_ + c) =
                make_float2(acc[mt][nt][0], acc[mt][nt][1]);
            *(float2*)(g_Wh + (size_t)(r0 + 8) * HF_ + c) =
                make_float2(acc[mt][nt][2], acc[mt][nt][3]);
        }
    }
}

// ---------------------------------------------------------------------------
// K2: per (row,h): src/dst dots + exp packing. Warp per task.
// ---------------------------------------------------------------------------
__global__ void __launch_bounds__(256) srcdst_kernel(const int* __restrict__ mask,
                                                     const float* __restrict__ a)
{
    __shared__ float asrc[64], adst[64];
    const int t = threadIdx.x;
    if (t < 64)       asrc[t]      = a[t];
    else if (t < 128) adst[t - 64] = a[t];
    __syncthreads();

    const int lane = t & 31;
    const int task = blockIdx.x * 8 + (t >> 5);
    const int row  = task >> 3;
    const int h    = task & 7;

    float2 v = *(const float2*)(g_Wh + (size_t)row * HF_ + h * F_ + lane * 2);
    float s = v.x * asrc[lane * 2] + v.y * asrc[lane * 2 + 1];
    float d = v.x * adst[lane * 2] + v.y * adst[lane * 2 + 1];
#pragma unroll
    for (int o = 16; o; o >>= 1) {
        s += __shfl_xor_sync(0xffffffffu, s, o);
        d += __shfl_xor_sync(0xffffffffu, d, o);
    }
    if (lane == 0) {
        const int b = row >> 10, i = row & 1023;
        const int idx = (b * H_ + h) * S_ + i;
        g_ipack[idx] = make_float4(s, expf(s), expf(ALPHA_ * s), 0.f);
        const float m = mask[row] ? 1.f : 0.f;
        g_jpack[idx] = make_float4(d, m * expf(d), m * expf(ALPHA_ * d), 0.f);
    }
}

// ---------------------------------------------------------------------------
// K3a: per (b,h): bitonic sort of (d_j, j) ascending. 1024 threads/block.
// ---------------------------------------------------------------------------
__global__ void __launch_bounds__(1024) sort_kernel()
{
    __shared__ float key[S_];
    __shared__ int   pidx[S_];
    const int bh = blockIdx.x;
    const int t  = threadIdx.x;

    key[t]  = g_jpack[bh * S_ + t].x;
    pidx[t] = t;
    __syncthreads();

    for (int k = 2; k <= S_; k <<= 1) {
        for (int j = k >> 1; j > 0; j >>= 1) {
            int ixj = t ^ j;
            if (ixj > t) {
                bool up = ((t & k) == 0);
                float a = key[t], b = key[ixj];
                bool sw = up ? (a > b) : (a < b);
                if (sw) {
                    key[t] = b; key[ixj] = a;
                    int tmp = pidx[t]; pidx[t] = pidx[ixj]; pidx[ixj] = tmp;
                }
            }
            __syncthreads();
        }
    }

    const int p = pidx[t];
    float4 jp = g_jpack[bh * S_ + p];
    g_dsorted[bh][t] = key[t];
    g_perm[bh][t]    = p;
    g_e1ds[bh][t]    = jp.y;
    g_eads[bh][t]    = jp.z;
}

// ---------------------------------------------------------------------------
// K3b-A: chunk partial sums. Block = (bh, chunk), 96 threads (c < 65 active).
// ---------------------------------------------------------------------------
__global__ void __launch_bounds__(96) scanA_kernel()
{
    __shared__ int   sp[CH_];
    __shared__ float sw0[CH_], sw1[CH_];
    const int bh = blockIdx.x;
    const int ch = blockIdx.y;
    const int b = bh >> 3, h = bh & 7;
    const int t = threadIdx.x;

    if (t < CH_) {
        const int kk = ch * CH_ + t;
        sp[t]  = g_perm[bh][kk] * HF_;
        sw0[t] = g_eads[bh][kk];
        sw1[t] = g_e1ds[bh][kk];
    }
    __syncthreads();
    if (t >= 65) return;

    const float* __restrict__ whb = g_Wh + (size_t)b * S_ * HF_ + h * F_ + t;
    const bool feat = (t < 64);
    float s0 = 0.f, s1 = 0.f;
#pragma unroll
    for (int k = 0; k < CH_; k++) {
        const float v = feat ? __ldg(whb + sp[k]) : 1.f;
        s0 += sw0[k] * v;
        s1 += sw1[k] * v;
    }
    g_csum0[bh][ch][t] = s0;
    g_csum1[bh][ch][t] = s1;
}

// ---------------------------------------------------------------------------
// K3b-B: per (bh, c): exclusive scan of the 32 chunk sums, in place.
// ---------------------------------------------------------------------------
__global__ void __launch_bounds__(96) scanB_kernel()
{
    const int bh = blockIdx.x;
    const int c  = threadIdx.x;
    if (c >= 65) return;

    float v0[NCH_], v1[NCH_];
#pragma unroll
    for (int ch = 0; ch < NCH_; ch++) {
        v0[ch] = g_csum0[bh][ch][c];
        v1[ch] = g_csum1[bh][ch][c];
    }
    float a0 = 0.f, a1 = 0.f;
#pragma unroll
    for (int ch = 0; ch < NCH_; ch++) {
        const float t0 = v0[ch], t1 = v1[ch];
        g_csum0[bh][ch][c] = a0;
        g_csum1[bh][ch][c] = a1;
        a0 += t0; a1 += t1;
    }
}

// ---------------------------------------------------------------------------
// K3b-C: materialize Q0/Q1 exclusive prefixes. Block = (bh, chunk), 96 thr.
// ---------------------------------------------------------------------------
__global__ void __launch_bounds__(96) scanC_kernel()
{
    __shared__ int   sp[CH_];
    __shared__ float sw0[CH_], sw1[CH_];
    const int bh = blockIdx.x;
    const int ch = blockIdx.y;
    const int b = bh >> 3, h = bh & 7;
    const int t = threadIdx.x;

    if (t < CH_) {
        const int kk = ch * CH_ + t;
        sp[t]  = g_perm[bh][kk] * HF_;
        sw0[t] = g_eads[bh][kk];
        sw1[t] = g_e1ds[bh][kk];
    }
    __syncthreads();
    if (t >= 65) return;

    const float* __restrict__ whb = g_Wh + (size_t)b * S_ * HF_ + h * F_ + t;
    const bool feat = (t < 64);
    const int k0 = ch * CH_;

    float off0 = g_csum0[bh][ch][t];
    float off1 = g_csum1[bh][ch][t];
#pragma unroll
    for (int k = 0; k < CH_; k++) {
        g_Q0[bh][k0 + k][t] = off0;
        g_Q1[bh][k0 + k][t] = off1;
        const float v = feat ? __ldg(whb + sp[k]) : 1.f;
        off0 += sw0[k] * v;
        off1 += sw1[k] * v;
    }
    if (ch == NCH_ - 1) {
        g_Q0[bh][S_][t] = off0;
        g_Q1[bh][S_][t] = off1;
    }
}

// ---------------------------------------------------------------------------
// K4: epilogue. Binary search split point; combine prefix/suffix; normalize.
// ---------------------------------------------------------------------------
__global__ void __launch_bounds__(256) out_kernel(float* __restrict__ out)
{
    __shared__ float ds[S_];
    const int b = blockIdx.z, h = blockIdx.y;
    const int bh = b * H_ + h;
    const int t = threadIdx.x;

    for (int q = t; q < S_; q += 256) ds[q] = g_dsorted[bh][q];
    __syncthreads();

    const int c4 = t & 15;
    const int il = t >> 4;
    const int i  = blockIdx.x * 16 + il;

    float4 ip = g_ipack[bh * S_ + i];
    const float e1s = ip.y, eas = ip.z;
    const float thr = -ip.x;

    int lo = 0, hi = S_;
    while (lo < hi) {
        int mid = (lo + hi) >> 1;
        if (ds[mid] < thr) lo = mid + 1; else hi = mid;
    }

    const float* q0 = &g_Q0[bh][lo][0];
    const float* q1 = &g_Q1[bh][lo][0];
    const float* t1 = &g_Q1[bh][S_][0];

    float4 n4 = *(const float4*)(q0 + c4 * 4);
    float4 q4 = *(const float4*)(q1 + c4 * 4);
    float4 t4 = *(const float4*)(t1 + c4 * 4);
    const float zpos = t1[64] - q1[64];
    const float inv = 1.f / (eas * q0[64] + e1s * zpos);

    float4 o;
    o.x = (eas * n4.x + e1s * (t4.x - q4.x)) * inv;
    o.y = (eas * n4.y + e1s * (t4.y - q4.y)) * inv;
    o.z = (eas * n4.z + e1s * (t4.z - q4.z)) * inv;
    o.w = (eas * n4.w + e1s * (t4.w - q4.w)) * inv;
    *(float4*)(out + (size_t)(b * S_ + i) * HF_ + h * F_ + c4 * 4) = o;
}

// ---------------------------------------------------------------------------
extern "C" void kernel_launch(void* const* d_in, const int* in_sizes, int n_in,
                              void* d_out, int out_size)
{
    const float* X    = (const float*)d_in[0];
    const int*   mask = (const int*)  d_in[1];
    const float* W    = (const float*)d_in[2];
    const float* a    = (const float*)d_in[3];
    float*       out  = (float*)d_out;

    static bool attr_set = false;
    if (!attr_set) {
        cudaFuncSetAttribute(mma_gemm_kernel,
                             cudaFuncAttributeMaxDynamicSharedMemorySize, 2 * STG_);
        attr_set = true;
    }

    convX_kernel<<<(B_ * S_ * IN_) / (256 * 4), 256>>>(X);
    convW_kernel<<<dim3(IN_ / 32, HF_ / 32), 256>>>(W);
    mma_gemm_kernel<<<dim3((B_ * S_) / 128, HF_ / 128), 256, 2 * STG_>>>();
    srcdst_kernel<<<(B_ * S_ * H_) / 8, 256>>>(mask, a);
    sort_kernel<<<BH_, 1024>>>();
    scanA_kernel<<<dim3(BH_, NCH_), 96>>>();
    scanB_kernel<<<BH_, 96>>>();
    scanC_kernel<<<dim3(BH_, NCH_), 96>>>();
    out_kernel<<<dim3(S_ / 16, H_, B_), 256>>>(out);
}